// round 12
// baseline (speedup 1.0000x reference)
#include <cuda_runtime.h>
#include <cstdint>

// Dice loss: pred (8,62,512,512) f32 logits, target (8,512,512) i32 -> scalar f32.
// Single HBM pass (520MB), single launch. R11 vs R9 (94.7us, DRAM 70.6%, issue 38%):
//  - 2 pixels/thread via float2 loads (halves LDG issue + address ALU per pixel)
//  - both pixels' exp packed in one bf16x2 reg per class (epk[62])
//  - et via direct reload of x[t] (L2 hit) instead of 124-op ISETP/SEL chain
//  - 152 blocks x 384 threads, 12 warps/SM, single wave

#define NC      62
#define HWV     (512 * 512)
#define NPIX    (8 * 512 * 512)
#define NQ      (NPIX / 2)
#define IGNORE  255
#define NBLK    152
#define NW      12             // warps per CTA
#define KP      512.0f
#define KPINV   (1.0f / 512.0f)

__device__ float g_pred_part[NC * NBLK];   // [c][b] per-CTA sum of softmax probs
__device__ float g_ic_part[NC * NBLK];     // [c][b] packed: KP*count + inter
__device__ unsigned g_ticket;              // zero-init; last CTA resets to 0

__global__ __launch_bounds__(384, 1)
void dice_main(const float* __restrict__ pred, const int* __restrict__ target,
               float* __restrict__ out) {
    __shared__ float s_ic[NC];     // packed inter+count, per class
    __shared__ float s1[NW][NC];   // per-warp staging for acc1 reduction
    __shared__ float sh_ds[NC];
    __shared__ float sh_nv[NC];
    __shared__ bool  s_last;

    for (int i = threadIdx.x; i < NC; i += 384) s_ic[i] = 0.f;
    __syncthreads();

    float acc1[NC];                // per-class sum of softmax probs (valid pixels)
#pragma unroll
    for (int c = 0; c < NC; ++c) acc1[c] = 0.f;

    const float L2E = 1.4426950408889634f;
    const int stride = gridDim.x * blockDim.x;

    for (int q = blockIdx.x * blockDim.x + threadIdx.x; q < NQ; q += stride) {
        const int p  = q << 1;               // first pixel of the pair
        const int n  = p >> 18;
        const int hw = p & (HWV - 1);        // even
        const float* base = pred + (size_t)n * (NC * HWV) + hw;

        const int2 tt = *(const int2*)(target + p);
        const bool v0 = (tt.x != IGNORE);
        const bool v1 = (tt.y != IGNORE);
        const int  t0 = v0 ? tt.x : 0;
        const int  t1 = v1 ? tt.y : 0;

        // prefetch logits at the target class (line is fetched this iter -> L2 hit)
        const float xt0 = __ldg(base + (size_t)t0 * HWV);
        const float xt1 = __ldg(base + (size_t)t1 * HWV + 1);

        uint32_t epk[NC];          // per class: bf16x2 {hi=pixel1, lo=pixel0}
        float d0 = 0.f, d1 = 0.f;

#pragma unroll
        for (int c = 0; c < NC; ++c) {
            const float2 x = __ldcs((const float2*)(base + (size_t)c * HWV));
            float ea, eb;
            asm("ex2.approx.ftz.f32 %0, %1;" : "=f"(ea) : "f"(x.x * L2E));
            asm("ex2.approx.ftz.f32 %0, %1;" : "=f"(eb) : "f"(x.y * L2E));
            d0 += ea;
            d1 += eb;
            uint32_t pk;
            asm("cvt.rn.bf16x2.f32 %0, %1, %2;" : "=r"(pk) : "f"(eb), "f"(ea));
            epk[c] = pk;
        }

        float inv0, inv1;
        asm("rcp.approx.ftz.f32 %0, %1;" : "=f"(inv0) : "f"(d0));
        asm("rcp.approx.ftz.f32 %0, %1;" : "=f"(inv1) : "f"(d1));
        const float i0 = v0 ? inv0 : 0.f;
        const float i1 = v1 ? inv1 : 0.f;

        // prob at target + packed count, one shared atomic per valid pixel
        float et0, et1;
        asm("ex2.approx.ftz.f32 %0, %1;" : "=f"(et0) : "f"(xt0 * L2E));
        asm("ex2.approx.ftz.f32 %0, %1;" : "=f"(et1) : "f"(xt1 * L2E));
        if (v0) atomicAdd(&s_ic[t0], fmaf(et0, inv0, KP));
        if (v1) atomicAdd(&s_ic[t1], fmaf(et1, inv1, KP));

#pragma unroll
        for (int c = 0; c < NC; ++c) {
            const uint32_t pk = epk[c];
            const float ea = __uint_as_float(pk << 16);
            const float eb = __uint_as_float(pk & 0xffff0000u);
            acc1[c] = fmaf(ea, i0, fmaf(eb, i1, acc1[c]));
        }
    }

    // Reduce acc1: warp butterfly per class -> shared -> per-CTA global slot.
    const int lane = threadIdx.x & 31;
    const int w    = threadIdx.x >> 5;
#pragma unroll
    for (int c = 0; c < NC; ++c) {
        float v = acc1[c];
#pragma unroll
        for (int s = 16; s; s >>= 1) v += __shfl_xor_sync(0xffffffffu, v, s);
        if (lane == 0) s1[w][c] = v;
    }
    __syncthreads();

    for (int c = threadIdx.x; c < NC; c += 384) {
        float a = 0.f;
#pragma unroll
        for (int ww = 0; ww < NW; ++ww) a += s1[ww][c];
        g_pred_part[c * NBLK + blockIdx.x] = a;
        g_ic_part[c * NBLK + blockIdx.x]   = s_ic[c];
    }

    // ---- threadfence reduction: last CTA does the final reduce ----
    __threadfence();
    if (threadIdx.x == 0) {
        const unsigned tk = atomicAdd(&g_ticket, 1u);
        s_last = (tk == NBLK - 1);
    }
    __syncthreads();
    if (!s_last) return;

    __threadfence();  // acquire: all CTAs' partials visible

    // 12 warps; warp w handles classes c = w, w+12, ... (L2-resident reads)
    for (int c = w; c < NC; c += NW) {
        float sp = 0.f, si = 0.f, sc = 0.f;
#pragma unroll
        for (int b = lane; b < NBLK; b += 32) {
            sp += g_pred_part[c * NBLK + b];
            const float v  = g_ic_part[c * NBLK + b];
            const float cf = floorf(v * KPINV);
            si = fmaf(-KP, cf, v) + si;   // inter part
            sc += cf;                      // count part
        }
#pragma unroll
        for (int s = 16; s; s >>= 1) {
            sp += __shfl_xor_sync(0xffffffffu, sp, s);
            si += __shfl_xor_sync(0xffffffffu, si, s);
            sc += __shfl_xor_sync(0xffffffffu, sc, s);
        }
        if (lane == 0) {
            const float u    = sp + sc;
            const float dice = (2.f * si + 1e-6f) / (u + 1e-6f);
            sh_ds[c] = (u > 0.f) ? dice : 0.f;
            sh_nv[c] = (u > 0.f) ? 1.f : 0.f;
        }
    }
    __syncthreads();
    if (threadIdx.x == 0) {
        float ds = 0.f, nv = 0.f;
#pragma unroll
        for (int k = 0; k < NC; ++k) { ds += sh_ds[k]; nv += sh_nv[k]; }
        const float md = (nv > 0.f) ? (ds / fmaxf(nv, 1.f)) : 1.f;
        out[0] = 1.f - md;
        g_ticket = 0;   // reset for next graph replay
    }
}

extern "C" void kernel_launch(void* const* d_in, const int* in_sizes, int n_in,
                              void* d_out, int out_size) {
    const float* pred   = (const float*)d_in[0];
    const int*   target = (const int*)d_in[1];
    float*       out    = (float*)d_out;

    dice_main<<<NBLK, 384>>>(pred, target, out);
}